// round 8
// baseline (speedup 1.0000x reference)
#include <cuda_runtime.h>
#include <math.h>

#define D 64
#define TWOD 128
#define RD 256            // RANK*D
#define W1S 68            // padded stride for W1 rows (== 4 mod 32: conflict-free quarter-warp phases)
#define W2S 132           // padded stride for W2 rows (== 4 mod 32)
#define WARPS 8
#define THREADS 256
#define BROWS 24          // rows per block-iteration (block-cooperative)
#define SLOT 512          // per-row scratch: xv(128, later du/partials) + hs(128, later partials) + wg(256: m->wm->g)

#define SMEM_FLOATS (TWOD*W1S + RD*W2S + TWOD + RD + BROWS*SLOT)

__device__ __forceinline__ float my_tanh(float x) {
    float xc = fminf(fmaxf(x, -10.0f), 10.0f);
    float e = __expf(2.0f * xc);
    return __fdividef(e - 1.0f, e + 1.0f);
}

__global__ __launch_bounds__(THREADS, 1)
void geognn_grad_kernel(const float* __restrict__ input,
                        const float* __restrict__ W1, const float* __restrict__ b1,
                        const float* __restrict__ W2, const float* __restrict__ b2,
                        float* __restrict__ out, int n)
{
    extern __shared__ float smem[];
    float* W1s = smem;                      // [128][68]
    float* W2s = W1s + TWOD * W1S;          // [256][132]
    float* b1s = W2s + RD * W2S;            // [128]
    float* b2s = b1s + TWOD;                // [256]
    float* scr = b2s + RD;                  // BROWS slots of SLOT floats

    const int tid = threadIdx.x;
    const int w   = tid >> 5;
    const int l   = tid & 31;

    // ---- cooperative weight staging ----
    {
        const float4* W1v = (const float4*)W1;
        for (int i = tid; i < TWOD * (D / 4); i += THREADS) {
            int j = i >> 4, k4 = i & 15;
            *(float4*)(W1s + j * W1S + 4 * k4) = W1v[i];
        }
        const float4* W2v = (const float4*)W2;
        for (int i = tid; i < RD * (TWOD / 4); i += THREADS) {
            int j = i >> 5, k4 = i & 31;
            *(float4*)(W2s + j * W2S + 4 * k4) = W2v[i];
        }
        for (int i = tid; i < TWOD; i += THREADS) b1s[i] = b1[i];
        for (int i = tid; i < RD;   i += THREADS) b2s[i] = b2[i];
    }
    __syncthreads();

    const long step = (long)gridDim.x * BROWS;

    for (long base = (long)blockIdx.x * BROWS; base < n; base += step) {
        __syncthreads();   // protect scratch vs previous iteration's readers

        // ==== stage 0: load x|v for 24 rows (warp = one row, coalesced) ====
        for (int idx = tid; idx < BROWS * 32; idx += THREADS) {
            int r = idx >> 5, c = idx & 31;
            int row = (int)base + r; if (row >= n) row = n - 1;
            ((float4*)(scr + r * SLOT))[c] = ((const float4*)(input + (size_t)row * TWOD))[c];
        }
        __syncthreads();

        // ==== stage 1: h = tanh(W1 @ x + b1) — thread owns output j, 12 rows ====
        {
            const int j  = tid & 127;
            const int r0 = (tid >> 7) * 12;
            float acc[12];
            const float bj = b1s[j];
            #pragma unroll
            for (int r = 0; r < 12; r++) acc[r] = bj;
            const float* wrow = W1s + j * W1S;
            #pragma unroll 4
            for (int k = 0; k < D; k += 4) {
                float4 q = *(const float4*)(wrow + k);
                #pragma unroll
                for (int r = 0; r < 12; r++) {
                    float4 xk = *(const float4*)(scr + (r0 + r) * SLOT + k);   // broadcast
                    acc[r] = fmaf(q.x, xk.x, acc[r]); acc[r] = fmaf(q.y, xk.y, acc[r]);
                    acc[r] = fmaf(q.z, xk.z, acc[r]); acc[r] = fmaf(q.w, xk.w, acc[r]);
                }
            }
            #pragma unroll
            for (int r = 0; r < 12; r++)
                scr[(r0 + r) * SLOT + 128 + j] = my_tanh(acc[r]);
        }
        __syncthreads();

        // ==== stage 2: wm = tanh(W2 @ h + b2) — thread owns j and j+128, 12 rows ====
        {
            const int jp = tid & 127;
            const int r0 = (tid >> 7) * 12;
            float acca[12], accb[12];
            const float ba = b2s[jp], bb = b2s[jp + 128];
            #pragma unroll
            for (int r = 0; r < 12; r++) { acca[r] = ba; accb[r] = bb; }
            const float* w2a = W2s + jp * W2S;
            const float* w2b = W2s + (jp + 128) * W2S;
            #pragma unroll 2
            for (int k = 0; k < TWOD; k += 4) {
                float4 qa = *(const float4*)(w2a + k);
                float4 qb = *(const float4*)(w2b + k);
                #pragma unroll
                for (int r = 0; r < 12; r++) {
                    float4 hk = *(const float4*)(scr + (r0 + r) * SLOT + 128 + k);  // broadcast
                    acca[r] = fmaf(qa.x, hk.x, acca[r]); acca[r] = fmaf(qa.y, hk.y, acca[r]);
                    acca[r] = fmaf(qa.z, hk.z, acca[r]); acca[r] = fmaf(qa.w, hk.w, acca[r]);
                    accb[r] = fmaf(qb.x, hk.x, accb[r]); accb[r] = fmaf(qb.y, hk.y, accb[r]);
                    accb[r] = fmaf(qb.z, hk.z, accb[r]); accb[r] = fmaf(qb.w, hk.w, accb[r]);
                }
            }
            #pragma unroll
            for (int r = 0; r < 12; r++) {
                scr[(r0 + r) * SLOT + 256 + jp]       = my_tanh(acca[r]);
                scr[(r0 + r) * SLOT + 256 + jp + 128] = my_tanh(accb[r]);
            }
        }
        __syncthreads();

        // ==== middle: y, g, dv — per-warp, 3 rows per warp (wm register-resident) ====
        {
            #pragma unroll
            for (int rr = 0; rr < 3; rr++) {
                const int r = w * 3 + rr;
                float* sl = scr + r * SLOT;
                float wm[8], vi[8];
                #pragma unroll
                for (int t = 0; t < 8; t++) wm[t] = sl[256 + l + 32 * t];
                #pragma unroll
                for (int t = 0; t < 8; t++) vi[t] = sl[64 + (l >> 2) + 8 * t];

                float y = 0.f;
                #pragma unroll
                for (int t = 0; t < 8; t++) y = fmaf(vi[t], wm[t], y);
                y += __shfl_xor_sync(0xffffffffu, y, 4);
                y += __shfl_xor_sync(0xffffffffu, y, 8);
                y += __shfl_xor_sync(0xffffffffu, y, 16);   // y = y[l&3]

                int row = (int)base + r; if (row >= n) row = n - 1;
                float* outrow = out + (size_t)row * TWOD;
                #pragma unroll
                for (int t = 0; t < 8; t++) {
                    float p = y * wm[t];
                    p += __shfl_xor_sync(0xffffffffu, p, 1);
                    p += __shfl_xor_sync(0xffffffffu, p, 2);
                    if ((l & 3) == 0) outrow[D + (l >> 2) + 8 * t] = -2.0f * p;
                    sl[256 + l + 32 * t] = 2.0f * y * vi[t] * (1.0f - wm[t] * wm[t]);  // g overlays wm
                }
            }
        }
        __syncthreads();

        // ==== stage 3: dh = W2^T @ g ; du = dh*(1-h^2) — split j in halves across warp pairs ====
        {
            const int c  = tid & 31;          // k-chunk 4c..4c+3
            const int jg = (tid >> 5) & 1;    // j-half
            const int rb = (tid >> 6) * 6;    // 6 rows per group
            float4 acc[6];
            #pragma unroll
            for (int r = 0; r < 6; r++) acc[r] = make_float4(0.f, 0.f, 0.f, 0.f);
            const int j0 = jg * 128;
            #pragma unroll 2
            for (int jq = 0; jq < 32; jq++) {
                const int j = j0 + 4 * jq;
                const float* wp = W2s + j * W2S + 4 * c;
                float4 q0 = *(const float4*)(wp);
                float4 q1 = *(const float4*)(wp + W2S);
                float4 q2 = *(const float4*)(wp + 2 * W2S);
                float4 q3 = *(const float4*)(wp + 3 * W2S);
                #pragma unroll
                for (int r = 0; r < 6; r++) {
                    float4 gq = *(const float4*)(scr + (rb + r) * SLOT + 256 + j);   // broadcast
                    acc[r].x = fmaf(gq.x, q0.x, acc[r].x); acc[r].x = fmaf(gq.y, q1.x, acc[r].x);
                    acc[r].x = fmaf(gq.z, q2.x, acc[r].x); acc[r].x = fmaf(gq.w, q3.x, acc[r].x);
                    acc[r].y = fmaf(gq.x, q0.y, acc[r].y); acc[r].y = fmaf(gq.y, q1.y, acc[r].y);
                    acc[r].y = fmaf(gq.z, q2.y, acc[r].y); acc[r].y = fmaf(gq.w, q3.y, acc[r].y);
                    acc[r].z = fmaf(gq.x, q0.z, acc[r].z); acc[r].z = fmaf(gq.y, q1.z, acc[r].z);
                    acc[r].z = fmaf(gq.z, q2.z, acc[r].z); acc[r].z = fmaf(gq.w, q3.z, acc[r].z);
                    acc[r].w = fmaf(gq.x, q0.w, acc[r].w); acc[r].w = fmaf(gq.y, q1.w, acc[r].w);
                    acc[r].w = fmaf(gq.z, q2.w, acc[r].w); acc[r].w = fmaf(gq.w, q3.w, acc[r].w);
                }
            }
            if (jg) {   // write partials into dead x|v region
                #pragma unroll
                for (int r = 0; r < 6; r++)
                    *(float4*)(scr + (rb + r) * SLOT + 4 * c) = acc[r];
            }
            __syncthreads();
            if (!jg) {  // combine, apply (1-h^2), write du in-place
                #pragma unroll
                for (int r = 0; r < 6; r++) {
                    float* px = scr + (rb + r) * SLOT;
                    float4 part = *(const float4*)(px + 4 * c);
                    float4 hk   = *(const float4*)(px + 128 + 4 * c);
                    float4 du;
                    du.x = (acc[r].x + part.x) * (1.0f - hk.x * hk.x);
                    du.y = (acc[r].y + part.y) * (1.0f - hk.y * hk.y);
                    du.z = (acc[r].z + part.z) * (1.0f - hk.z * hk.z);
                    du.w = (acc[r].w + part.w) * (1.0f - hk.w * hk.w);
                    *(float4*)(px + 4 * c) = du;
                }
            }
        }
        __syncthreads();

        // ==== stage 4: dx = W1^T @ du — split j in halves across warp pairs ====
        {
            const int c  = tid & 31;          // i = 2c, 2c+1
            const int jg = (tid >> 5) & 1;
            const int rb = (tid >> 6) * 6;
            float a0[6], a1[6];
            #pragma unroll
            for (int r = 0; r < 6; r++) { a0[r] = 0.f; a1[r] = 0.f; }
            const int j0 = jg * 64;
            #pragma unroll 2
            for (int jq = 0; jq < 16; jq++) {
                const int j = j0 + 4 * jq;
                const float* wp = W1s + j * W1S + 2 * c;
                float2 c0 = *(const float2*)(wp);
                float2 c1 = *(const float2*)(wp + W1S);
                float2 c2 = *(const float2*)(wp + 2 * W1S);
                float2 c3 = *(const float2*)(wp + 3 * W1S);
                #pragma unroll
                for (int r = 0; r < 6; r++) {
                    float4 dq = *(const float4*)(scr + (rb + r) * SLOT + j);   // du broadcast
                    a0[r] = fmaf(dq.x, c0.x, a0[r]); a0[r] = fmaf(dq.y, c1.x, a0[r]);
                    a0[r] = fmaf(dq.z, c2.x, a0[r]); a0[r] = fmaf(dq.w, c3.x, a0[r]);
                    a1[r] = fmaf(dq.x, c0.y, a1[r]); a1[r] = fmaf(dq.y, c1.y, a1[r]);
                    a1[r] = fmaf(dq.z, c2.y, a1[r]); a1[r] = fmaf(dq.w, c3.y, a1[r]);
                }
            }
            if (jg) {   // partials into dead hs region
                #pragma unroll
                for (int r = 0; r < 6; r++)
                    *(float2*)(scr + (rb + r) * SLOT + 128 + 2 * c) = make_float2(a0[r], a1[r]);
            }
            __syncthreads();
            if (!jg) {  // combine + write dx to global
                #pragma unroll
                for (int r = 0; r < 6; r++) {
                    int row = (int)base + rb + r; if (row >= n) row = n - 1;
                    float2 p = *(const float2*)(scr + (rb + r) * SLOT + 128 + 2 * c);
                    *(float2*)(out + (size_t)row * TWOD + 2 * c) =
                        make_float2(a0[r] + p.x, a1[r] + p.y);
                }
            }
        }
    }
}

extern "C" void kernel_launch(void* const* d_in, const int* in_sizes, int n_in,
                              void* d_out, int out_size) {
    // inputs: t(1), input_(N*128), W1(128*64), b1(128), W2(256*128), b2(256)
    const float* input = (const float*)d_in[1];
    const float* W1    = (const float*)d_in[2];
    const float* b1    = (const float*)d_in[3];
    const float* W2    = (const float*)d_in[4];
    const float* b2    = (const float*)d_in[5];
    float* out = (float*)d_out;
    const int n = in_sizes[1] / TWOD;

    static_assert(SMEM_FLOATS * 4 < 232448, "smem budget");

    int dev = 0;
    cudaGetDevice(&dev);
    int nsm = 148;
    cudaDeviceGetAttribute(&nsm, cudaDevAttrMultiProcessorCount, dev);

    cudaFuncSetAttribute(geognn_grad_kernel,
                         cudaFuncAttributeMaxDynamicSharedMemorySize,
                         SMEM_FLOATS * (int)sizeof(float));

    geognn_grad_kernel<<<nsm, THREADS, SMEM_FLOATS * (int)sizeof(float)>>>(
        input, W1, b1, W2, b2, out, n);
}